// round 2
// baseline (speedup 1.0000x reference)
#include <cuda_runtime.h>
#include <math.h>

// ---------------------------------------------------------------------------
// PACE module: B=32768 independent small problems sharing a precompute from b.
// Structure exploited:  M = C*A - [I;0],  C=[2*barB; 2*sqrt(lam)*I8],
// A = G*barB^T.  With Sum(g)=1 and 1^T G = 0 (exact identities):
//   q_top[e]   = -g . P[:,e]
//   Q_low[e,f] = delta(j_e==j_f)*Y2c[m_e,m_f] - 2 * P[:,e]^T G P[:,f]
//   c[k]       = g[k] + 2*sum_{i,j} R[j][i]*D[k][3i+j],  D = G*P
// where P[k,(j,m)] = sum_n w_n (b[k,j,n]-bw[k,j]) * y[m,n]  (no centering of y
// needed because rows of barB/A annihilate constants).
// ---------------------------------------------------------------------------

struct PreData {
    float bb2[64 * 24];   // [n][k*3+j] = w_n*(b[k,j,n]-bw[k,j])
    float G[64];          // 8x8
    float g[8];
    float bw[24];         // [k*3+j]
    float Q00;
    float wsum;
};
__device__ PreData g_pre;

// ------------------------------- precompute --------------------------------
__global__ void pace_precompute(const float* __restrict__ bp,
                                const float* __restrict__ wp,
                                const float* __restrict__ lamp) {
    __shared__ float s_w[64];
    __shared__ float s_wsum;
    __shared__ float s_bw[24];
    __shared__ float s_barb[24][64];   // sqrt(w)*(b - bw), [k*3+j][n]
    __shared__ float s_BtB[36];
    int tid = threadIdx.x;
    if (tid < 64) s_w[tid] = wp[tid];
    __syncthreads();
    if (tid == 0) {
        float acc = 0.f;
        for (int n = 0; n < 64; n++) acc += s_w[n];
        s_wsum = acc;
    }
    __syncthreads();
    if (tid < 24) {
        int k = tid / 3, j = tid % 3;
        float acc = 0.f;
        for (int n = 0; n < 64; n++) acc += bp[k * 192 + j * 64 + n] * s_w[n];
        s_bw[tid] = acc / s_wsum;
    }
    __syncthreads();
    for (int i = tid; i < 1536; i += blockDim.x) {
        int kj = i >> 6, n = i & 63;
        int k = kj / 3, j = kj % 3;
        float bb = bp[k * 192 + j * 64 + n] - s_bw[kj];
        s_barb[kj][n] = sqrtf(s_w[n]) * bb;
        g_pre.bb2[n * 24 + kj] = s_w[n] * bb;
    }
    __syncthreads();
    if (tid < 36) {
        int k1 = 0, rem = tid;
        while (rem >= 8 - k1) { rem -= 8 - k1; k1++; }
        int k2 = k1 + rem;
        float acc = 0.f;
        for (int j = 0; j < 3; j++)
            for (int n = 0; n < 64; n++)
                acc += s_barb[k1 * 3 + j][n] * s_barb[k2 * 3 + j][n];
        s_BtB[tid] = acc;
    }
    __syncthreads();
    if (tid == 0) {
        float lam = lamp[0];
        float H[8][8];
        int idx = 0;
        for (int a = 0; a < 8; a++)
            for (int b2 = a; b2 < 8; b2++) {
                float v = s_BtB[idx++];
                H[a][b2] = v; H[b2][a] = v;
            }
        for (int a = 0; a < 8; a++)
            for (int b2 = 0; b2 < 8; b2++)
                H[a][b2] = 2.f * (H[a][b2] + ((a == b2) ? lam : 0.f));
        // invert 8x8 (Gauss-Jordan with partial pivoting)
        float M[8][16];
        for (int r = 0; r < 8; r++)
            for (int c = 0; c < 16; c++)
                M[r][c] = (c < 8) ? H[r][c] : ((c - 8 == r) ? 1.f : 0.f);
        for (int col = 0; col < 8; col++) {
            int piv = col; float best = fabsf(M[col][col]);
            for (int r = col + 1; r < 8; r++) {
                float v = fabsf(M[r][col]);
                if (v > best) { best = v; piv = r; }
            }
            if (piv != col)
                for (int c = 0; c < 16; c++) {
                    float tv = M[col][c]; M[col][c] = M[piv][c]; M[piv][c] = tv;
                }
            float inv = 1.f / M[col][col];
            for (int c = 0; c < 16; c++) M[col][c] *= inv;
            for (int r = 0; r < 8; r++)
                if (r != col) {
                    float f = M[r][col];
                    for (int c = 0; c < 16; c++) M[r][c] -= f * M[col][c];
                }
        }
        float Ht[8]; float s = 0.f;
        for (int a = 0; a < 8; a++) {
            float acc = 0.f;
            for (int b2 = 0; b2 < 8; b2++) acc += M[a][8 + b2];
            Ht[a] = acc; s += acc;
        }
        float inv_s = 1.f / s;
        float gv[8];
        for (int a = 0; a < 8; a++) { gv[a] = Ht[a] * inv_s; g_pre.g[a] = gv[a]; }
        for (int a = 0; a < 8; a++)
            for (int b2 = 0; b2 < 8; b2++)
                g_pre.G[a * 8 + b2] = M[a][8 + b2] - Ht[a] * Ht[b2] * inv_s;
        for (int i2 = 0; i2 < 24; i2++) g_pre.bw[i2] = s_bw[i2];
        // Q00 = h.h  with h = [barB g ; sqrt(lam) g]
        float q00 = 0.f;
        for (int j = 0; j < 3; j++)
            for (int n = 0; n < 64; n++) {
                float hb = 0.f;
                for (int k = 0; k < 8; k++) hb += s_barb[k * 3 + j][n] * gv[k];
                q00 += hb * hb;
            }
        float gg = 0.f;
        for (int k = 0; k < 8; k++) gg += gv[k] * gv[k];
        q00 += lam * gg;
        g_pre.Q00 = q00;
        g_pre.wsum = s_wsum;
    }
}

// ------------------------------ main kernel --------------------------------
// symmetric 10x10 upper-tri index (i<=j)
__device__ __forceinline__ constexpr int QI(int i, int j) {
    return 9 * i - (i * (i - 1)) / 2 + j;
}
__device__ __forceinline__ float& symA(float* A_, int i, int j) {
    return (i <= j) ? A_[QI(i, j)] : A_[QI(j, i)];
}

template <int P, int Q>
__device__ __forceinline__ void jrot(float* A_, float V[10][10]) {
    float apq = A_[QI(P, Q)];
    float app = A_[QI(P, P)];
    float aqq = A_[QI(Q, Q)];
    float theta = __fdividef((aqq - app) * 0.5f, apq);       // inf/NaN safe below
    float sq = sqrtf(theta * theta + 1.0f);
    float tt = __fdividef(1.0f, fabsf(theta) + sq);          // theta=inf -> 0
    tt = copysignf(tt, theta);
    tt = (apq == 0.0f) ? 0.0f : tt;                          // kill NaN case
    float cc = __frsqrt_rn(tt * tt + 1.0f);
    float ss = tt * cc;
#pragma unroll
    for (int r = 0; r < 10; r++) {
        if (r == P || r == Q) continue;
        float arp = symA(A_, r, P), arq = symA(A_, r, Q);
        symA(A_, r, P) = cc * arp - ss * arq;
        symA(A_, r, Q) = ss * arp + cc * arq;
    }
    A_[QI(P, P)] = app - tt * apq;
    A_[QI(Q, Q)] = aqq + tt * apq;
    A_[QI(P, Q)] = 0.0f;
#pragma unroll
    for (int r = 0; r < 10; r++) {
        float vrp = V[r][P], vrq = V[r][Q];
        V[r][P] = cc * vrp - ss * vrq;
        V[r][Q] = ss * vrp + cc * vrq;
    }
}

#define R2(p, q) jrot<p, q>(A_, Vv);

__global__ __launch_bounds__(128) void pace_main(const float* __restrict__ y,
                                                 const float* __restrict__ wp,
                                                 float* __restrict__ out,
                                                 int Bc) {
    __shared__ float bb2s[64][24];
    __shared__ float Dsh[72 * 128];     // D[k*9+e] per thread column
    __shared__ float Gs[64];
    __shared__ float gs[8];
    __shared__ float bws[24];
    __shared__ float ws[64];
    __shared__ float sQ00, swsum;
    int tid = threadIdx.x;
    for (int i = tid; i < 1536; i += 128) ((float*)bb2s)[i] = g_pre.bb2[i];
    if (tid < 64) Gs[tid] = g_pre.G[tid];
    if (tid < 8) gs[tid] = g_pre.g[tid];
    if (tid < 24) bws[tid] = g_pre.bw[tid];
    if (tid < 64) ws[tid] = wp[tid];
    if (tid == 0) { sQ00 = g_pre.Q00; swsum = g_pre.wsum; }
    __syncthreads();

    int b = blockIdx.x * 128 + tid;
    if (b >= Bc) return;
    const float* yb = y + (size_t)b * 192;

    // ---- stream y: accumulate s1, S2, P ----
    float P[8][9];
#pragma unroll
    for (int k = 0; k < 8; k++)
#pragma unroll
        for (int e = 0; e < 9; e++) P[k][e] = 0.f;
    float s1[3] = {0.f, 0.f, 0.f};
    float S2[6] = {0.f, 0.f, 0.f, 0.f, 0.f, 0.f};
#pragma unroll 4
    for (int n4 = 0; n4 < 16; n4++) {
        float4 a0 = *(const float4*)(yb + 4 * n4);
        float4 a1 = *(const float4*)(yb + 64 + 4 * n4);
        float4 a2 = *(const float4*)(yb + 128 + 4 * n4);
        float v0[4] = {a0.x, a0.y, a0.z, a0.w};
        float v1[4] = {a1.x, a1.y, a1.z, a1.w};
        float v2[4] = {a2.x, a2.y, a2.z, a2.w};
#pragma unroll
        for (int s = 0; s < 4; s++) {
            int n = 4 * n4 + s;
            float y0 = v0[s], y1 = v1[s], y2 = v2[s];
            float wv = ws[n];
            float wy0 = wv * y0, wy1 = wv * y1, wy2 = wv * y2;
            s1[0] += wy0; s1[1] += wy1; s1[2] += wy2;
            S2[0] += wy0 * y0; S2[1] += wy0 * y1; S2[2] += wy0 * y2;
            S2[3] += wy1 * y1; S2[4] += wy1 * y2; S2[5] += wy2 * y2;
            const float* bbn = bb2s[n];
#pragma unroll
            for (int k = 0; k < 8; k++) {
#pragma unroll
                for (int j = 0; j < 3; j++) {
                    float bv = bbn[k * 3 + j];
                    P[k][3 * j + 0] += bv * y0;
                    P[k][3 * j + 1] += bv * y1;
                    P[k][3 * j + 2] += bv * y2;
                }
            }
        }
    }
    float inv_wsum = __fdividef(1.f, swsum);
    float ym[3] = {s1[0] * inv_wsum, s1[1] * inv_wsum, s1[2] * inv_wsum};

    // ---- D = G * P  (stash in shared, needed again after eigensolve) ----
#pragma unroll
    for (int k = 0; k < 8; k++) {
#pragma unroll
        for (int e = 0; e < 9; e++) {
            float acc = 0.f;
#pragma unroll
            for (int k2 = 0; k2 < 8; k2++) acc += Gs[k * 8 + k2] * P[k2][e];
            Dsh[(k * 9 + e) * 128 + tid] = acc;
        }
    }

    // ---- build Q (10x10 symmetric, upper-tri storage) ----
    float A_[55];
    A_[QI(0, 0)] = sQ00;
#pragma unroll
    for (int e = 0; e < 9; e++) {
        float acc = 0.f;
#pragma unroll
        for (int k = 0; k < 8; k++) acc += gs[k] * P[k][e];
        A_[QI(0, 1 + e)] = -acc;
    }
    float Y2c[6];
    Y2c[0] = S2[0] - s1[0] * s1[0] * inv_wsum;
    Y2c[1] = S2[1] - s1[0] * s1[1] * inv_wsum;
    Y2c[2] = S2[2] - s1[0] * s1[2] * inv_wsum;
    Y2c[3] = S2[3] - s1[1] * s1[1] * inv_wsum;
    Y2c[4] = S2[4] - s1[1] * s1[2] * inv_wsum;
    Y2c[5] = S2[5] - s1[2] * s1[2] * inv_wsum;
#pragma unroll
    for (int e = 0; e < 9; e++) {
#pragma unroll
        for (int f = 0; f < 9; f++) {
            if (f < e) continue;
            float acc = 0.f;
#pragma unroll
            for (int k = 0; k < 8; k++)
                acc += P[k][e] * Dsh[(k * 9 + f) * 128 + tid];
            float val = -2.f * acc;
            int je = e / 3, me = e % 3, jf = f / 3, mf = f % 3;
            if (je == jf) {
                int a = (me <= mf) ? me : mf;
                int b2 = (me <= mf) ? mf : me;
                val += Y2c[3 * a - (a * (a + 1)) / 2 + b2];
            }
            A_[QI(1 + e, 1 + f)] = val;
        }
    }

    // ---- cyclic Jacobi, 7 sweeps, eigenvectors in Vv columns ----
    float Vv[10][10];
#pragma unroll
    for (int i = 0; i < 10; i++)
#pragma unroll
        for (int j = 0; j < 10; j++) Vv[i][j] = (i == j) ? 1.f : 0.f;
    for (int sweep = 0; sweep < 7; sweep++) {
        R2(0,1) R2(0,2) R2(0,3) R2(0,4) R2(0,5) R2(0,6) R2(0,7) R2(0,8) R2(0,9)
        R2(1,2) R2(1,3) R2(1,4) R2(1,5) R2(1,6) R2(1,7) R2(1,8) R2(1,9)
        R2(2,3) R2(2,4) R2(2,5) R2(2,6) R2(2,7) R2(2,8) R2(2,9)
        R2(3,4) R2(3,5) R2(3,6) R2(3,7) R2(3,8) R2(3,9)
        R2(4,5) R2(4,6) R2(4,7) R2(4,8) R2(4,9)
        R2(5,6) R2(5,7) R2(5,8) R2(5,9)
        R2(6,7) R2(6,8) R2(6,9)
        R2(7,8) R2(7,9)
        R2(8,9)
    }

    // ---- pick eigenvector of smallest eigenvalue ----
    int best = 0; float bd = A_[QI(0, 0)];
#pragma unroll
    for (int i = 1; i < 10; i++) {
        float d = A_[QI(i, i)];
        if (d < bd) { bd = d; best = i; }
    }
    float vec[10];
#pragma unroll
    for (int r = 0; r < 10; r++) vec[r] = Vv[r][0];
#pragma unroll
    for (int cI = 1; cI < 10; cI++) {
        bool sel = (best == cI);
#pragma unroll
        for (int r = 0; r < 10; r++) vec[r] = sel ? Vv[r][cI] : vec[r];
    }
    float inv0 = __fdividef(1.f, vec[0]);
    float R_[3][3];
#pragma unroll
    for (int i = 0; i < 3; i++)
#pragma unroll
        for (int j = 0; j < 3; j++) R_[i][j] = vec[1 + 3 * j + i] * inv0;

    // ---- c, t ----
    float c_[8];
#pragma unroll
    for (int k = 0; k < 8; k++) {
        float acc = gs[k];
#pragma unroll
        for (int i = 0; i < 3; i++)
#pragma unroll
            for (int j = 0; j < 3; j++)
                acc += 2.f * R_[j][i] * Dsh[(k * 9 + 3 * i + j) * 128 + tid];
        c_[k] = acc;
    }
    float u[3];
#pragma unroll
    for (int j = 0; j < 3; j++) {
        float acc = 0.f;
#pragma unroll
        for (int k = 0; k < 8; k++) acc += bws[k * 3 + j] * c_[k];
        u[j] = acc;
    }
    float tv[3];
#pragma unroll
    for (int i = 0; i < 3; i++)
        tv[i] = ym[i] - (R_[i][0] * u[0] + R_[i][1] * u[1] + R_[i][2] * u[2]);

    // ---- outputs: [R (B*9) | t (B*3) | c (B*8)] ----
    float* oR = out;
    float* oT = out + (size_t)Bc * 9;
    float* oC = out + (size_t)Bc * 12;
#pragma unroll
    for (int i = 0; i < 3; i++)
#pragma unroll
        for (int j = 0; j < 3; j++) oR[(size_t)b * 9 + i * 3 + j] = R_[i][j];
#pragma unroll
    for (int i = 0; i < 3; i++) oT[(size_t)b * 3 + i] = tv[i];
#pragma unroll
    for (int k = 0; k < 8; k++) oC[(size_t)b * 8 + k] = c_[k];
}

// ------------------------------ launcher -----------------------------------
extern "C" void kernel_launch(void* const* d_in, const int* in_sizes, int n_in,
                              void* d_out, int out_size) {
    const float* y = (const float*)d_in[0];
    const float* b = (const float*)d_in[1];
    const float* w = (const float*)d_in[2];
    const float* lam = (const float*)d_in[3];
    int Bc = in_sizes[0] / 192;
    pace_precompute<<<1, 256>>>(b, w, lam);
    int blocks = (Bc + 127) / 128;
    pace_main<<<blocks, 128>>>(y, w, (float*)d_out, Bc);
}

// round 9
// speedup vs baseline: 1.4675x; 1.4675x over previous
#include <cuda_runtime.h>
#include <math.h>

// ---------------------------------------------------------------------------
// PACE module. Per-batch reduction:
//   P[k][3j+m] = sum_n w_n (b[k,j,n]-bw[k,j]) * y[m,n]
//   q_top[e]   = -g . P[:,e]
//   Q_low[e,f] = delta(j_e==j_f)*Y2c[m_e,m_f] - 2 * P[:,e]^T G P[:,f]
//   c[k]       = g[k] + 2*(G*Pr)[k],  Pr[k] = sum_e P[k][e]*R[e%3][e/3]
// Eigen: eigenvalue-only cyclic Jacobi (6 sweeps) -> lam_min; then LDL^T on
// S = Q - (lam - delta)*I  with delta = 1e-4*max|diag|  (S is PD => stable
// un-pivoted factorization), and two inverse-iteration solves (rescaled).
// ---------------------------------------------------------------------------

struct PreData {
    float bb2[64 * 24];   // [n][k*3+j] = w_n*(b[k,j,n]-bw[k,j])
    float G[64];          // 8x8
    float g[8];
    float bw[24];         // [k*3+j]
    float Q00;
    float wsum;
};
__device__ PreData g_pre;

// ------------------------------- precompute --------------------------------
__global__ void pace_precompute(const float* __restrict__ bp,
                                const float* __restrict__ wp,
                                const float* __restrict__ lamp) {
    __shared__ float s_w[64];
    __shared__ float s_wsum;
    __shared__ float s_bw[24];
    __shared__ float s_barb[24][64];
    __shared__ float s_BtB[36];
    int tid = threadIdx.x;
    if (tid < 64) s_w[tid] = wp[tid];
    __syncthreads();
    if (tid == 0) {
        float acc = 0.f;
        for (int n = 0; n < 64; n++) acc += s_w[n];
        s_wsum = acc;
    }
    __syncthreads();
    if (tid < 24) {
        int k = tid / 3, j = tid % 3;
        float acc = 0.f;
        for (int n = 0; n < 64; n++) acc += bp[k * 192 + j * 64 + n] * s_w[n];
        s_bw[tid] = acc / s_wsum;
    }
    __syncthreads();
    for (int i = tid; i < 1536; i += blockDim.x) {
        int kj = i >> 6, n = i & 63;
        int k = kj / 3, j = kj % 3;
        float bb = bp[k * 192 + j * 64 + n] - s_bw[kj];
        s_barb[kj][n] = sqrtf(s_w[n]) * bb;
        g_pre.bb2[n * 24 + kj] = s_w[n] * bb;
    }
    __syncthreads();
    if (tid < 36) {
        int k1 = 0, rem = tid;
        while (rem >= 8 - k1) { rem -= 8 - k1; k1++; }
        int k2 = k1 + rem;
        float acc = 0.f;
        for (int j = 0; j < 3; j++)
            for (int n = 0; n < 64; n++)
                acc += s_barb[k1 * 3 + j][n] * s_barb[k2 * 3 + j][n];
        s_BtB[tid] = acc;
    }
    __syncthreads();
    if (tid == 0) {
        float lam = lamp[0];
        float H[8][8];
        int idx = 0;
        for (int a = 0; a < 8; a++)
            for (int b2 = a; b2 < 8; b2++) {
                float v = s_BtB[idx++];
                H[a][b2] = v; H[b2][a] = v;
            }
        for (int a = 0; a < 8; a++)
            for (int b2 = 0; b2 < 8; b2++)
                H[a][b2] = 2.f * (H[a][b2] + ((a == b2) ? lam : 0.f));
        float M[8][16];
        for (int r = 0; r < 8; r++)
            for (int c = 0; c < 16; c++)
                M[r][c] = (c < 8) ? H[r][c] : ((c - 8 == r) ? 1.f : 0.f);
        for (int col = 0; col < 8; col++) {
            int piv = col; float best = fabsf(M[col][col]);
            for (int r = col + 1; r < 8; r++) {
                float v = fabsf(M[r][col]);
                if (v > best) { best = v; piv = r; }
            }
            if (piv != col)
                for (int c = 0; c < 16; c++) {
                    float tv = M[col][c]; M[col][c] = M[piv][c]; M[piv][c] = tv;
                }
            float inv = 1.f / M[col][col];
            for (int c = 0; c < 16; c++) M[col][c] *= inv;
            for (int r = 0; r < 8; r++)
                if (r != col) {
                    float f = M[r][col];
                    for (int c = 0; c < 16; c++) M[r][c] -= f * M[col][c];
                }
        }
        float Ht[8]; float s = 0.f;
        for (int a = 0; a < 8; a++) {
            float acc = 0.f;
            for (int b2 = 0; b2 < 8; b2++) acc += M[a][8 + b2];
            Ht[a] = acc; s += acc;
        }
        float inv_s = 1.f / s;
        float gv[8];
        for (int a = 0; a < 8; a++) { gv[a] = Ht[a] * inv_s; g_pre.g[a] = gv[a]; }
        for (int a = 0; a < 8; a++)
            for (int b2 = 0; b2 < 8; b2++)
                g_pre.G[a * 8 + b2] = M[a][8 + b2] - Ht[a] * Ht[b2] * inv_s;
        for (int i2 = 0; i2 < 24; i2++) g_pre.bw[i2] = s_bw[i2];
        float q00 = 0.f;
        for (int j = 0; j < 3; j++)
            for (int n = 0; n < 64; n++) {
                float hb = 0.f;
                for (int k = 0; k < 8; k++) hb += s_barb[k * 3 + j][n] * gv[k];
                q00 += hb * hb;
            }
        float gg = 0.f;
        for (int k = 0; k < 8; k++) gg += gv[k] * gv[k];
        q00 += lam * gg;
        g_pre.Q00 = q00;
        g_pre.wsum = s_wsum;
    }
}

// ------------------------------ main kernel --------------------------------
__device__ __forceinline__ constexpr int QI(int i, int j) {
    return 9 * i - (i * (i - 1)) / 2 + j;
}
__device__ __forceinline__ float& symA(float* A_, int i, int j) {
    return (i <= j) ? A_[QI(i, j)] : A_[QI(j, i)];
}

// eigenvalue-only Jacobi rotation (3 MUFU ops, no vector update)
template <int P, int Q>
__device__ __forceinline__ void jrot(float* A_) {
    float apq = A_[QI(P, Q)];
    float app = A_[QI(P, P)];
    float aqq = A_[QI(Q, Q)];
    float del = 0.5f * (aqq - app);
    float h = sqrtf(del * del + apq * apq);
    float t = copysignf(1.0f, del) * __fdividef(apq, fabsf(del) + h + 1e-30f);
    float cc = __frsqrt_rn(t * t + 1.0f);
    float ss = t * cc;
#pragma unroll
    for (int r = 0; r < 10; r++) {
        if (r == P || r == Q) continue;
        float arp = symA(A_, r, P), arq = symA(A_, r, Q);
        symA(A_, r, P) = cc * arp - ss * arq;
        symA(A_, r, Q) = ss * arp + cc * arq;
    }
    A_[QI(P, P)] = app - t * apq;
    A_[QI(Q, Q)] = aqq + t * apq;
    A_[QI(P, Q)] = 0.0f;
}
#define R2(p, q) jrot<p, q>(A_);

// build S = Q - shift*I into A_[55], from P (regs), G/g (shared), Y2c, Q00
__device__ __forceinline__ void build_S(float* A_, const float P[8][9],
                                        const float* Gs, const float* gs,
                                        const float Y2c[6], float Q00,
                                        float shift) {
    A_[QI(0, 0)] = Q00 - shift;
#pragma unroll
    for (int e = 0; e < 9; e++) {
        float acc = 0.f;
#pragma unroll
        for (int k = 0; k < 8; k++) acc += gs[k] * P[k][e];
        A_[QI(0, 1 + e)] = -acc;
    }
#pragma unroll
    for (int f = 0; f < 9; f++) {
        float Df[8];
#pragma unroll
        for (int k = 0; k < 8; k++) {
            float acc = 0.f;
#pragma unroll
            for (int k2 = 0; k2 < 8; k2++) acc += Gs[k * 8 + k2] * P[k2][f];
            Df[k] = acc;
        }
#pragma unroll
        for (int e = 0; e <= f; e++) {
            float acc = 0.f;
#pragma unroll
            for (int k = 0; k < 8; k++) acc += P[k][e] * Df[k];
            float val = -2.f * acc;
            int je = e / 3, me = e % 3, jf = f / 3, mf = f % 3;
            if (je == jf) {
                int a = (me <= mf) ? me : mf;
                int b2 = (me <= mf) ? mf : me;
                val += Y2c[3 * a - (a * (a + 1)) / 2 + b2];
            }
            if (e == f) val -= shift;
            A_[QI(1 + e, 1 + f)] = val;
        }
    }
}

// solve S x = rhs using LDL^T factors stored in A_ (L strictly-upper as
// A_[QI(k,i)]=L[i][k] for k<i) and invd[].
__device__ __forceinline__ void ldl_solve(const float* A_, const float* invd,
                                          const float* rhs, float* x) {
    float z[10];
#pragma unroll
    for (int i = 0; i < 10; i++) {
        float acc = rhs[i];
#pragma unroll
        for (int k = 0; k < 10; k++) {
            if (k >= i) continue;
            acc -= A_[QI(k, i)] * z[k];   // L[i][k]
        }
        z[i] = acc;
    }
#pragma unroll
    for (int i = 0; i < 10; i++) z[i] *= invd[i];
#pragma unroll
    for (int i = 9; i >= 0; i--) {
        float acc = z[i];
#pragma unroll
        for (int j = 0; j < 10; j++) {
            if (j <= i) continue;
            acc -= A_[QI(i, j)] * x[j];
        }
        x[i] = acc;
    }
}

__global__ __launch_bounds__(32) void pace_main(const float* __restrict__ y,
                                                const float* __restrict__ wp,
                                                float* __restrict__ out,
                                                int Bc) {
    __shared__ float4 bb4s[64 * 6];            // [n][24] as 6 float4 per n
    __shared__ float Gs[64];
    __shared__ float gs[8];
    __shared__ float bws[24];
    __shared__ float ws[64];
    __shared__ float sQ00, swsum;
    int tid = threadIdx.x;
    {
        const float4* src = (const float4*)g_pre.bb2;
        for (int i = tid; i < 384; i += 32) bb4s[i] = src[i];
        for (int i = tid; i < 64; i += 32) Gs[i] = g_pre.G[i];
        if (tid < 8) gs[tid] = g_pre.g[tid];
        if (tid < 24) bws[tid] = g_pre.bw[tid];
        for (int i = tid; i < 64; i += 32) ws[i] = wp[i];
        if (tid == 0) { sQ00 = g_pre.Q00; swsum = g_pre.wsum; }
    }
    __syncthreads();

    int b = blockIdx.x * 32 + tid;
    if (b >= Bc) return;
    const float* yb = y + (size_t)b * 192;

    // ---- phase 1: stream y, accumulate s1, S2, P ----
    float P[8][9];
#pragma unroll
    for (int k = 0; k < 8; k++)
#pragma unroll
        for (int e = 0; e < 9; e++) P[k][e] = 0.f;
    float s1[3] = {0.f, 0.f, 0.f};
    float S2[6] = {0.f, 0.f, 0.f, 0.f, 0.f, 0.f};
#pragma unroll 4
    for (int n4 = 0; n4 < 16; n4++) {
        float4 a0 = *(const float4*)(yb + 4 * n4);
        float4 a1 = *(const float4*)(yb + 64 + 4 * n4);
        float4 a2 = *(const float4*)(yb + 128 + 4 * n4);
        float v0[4] = {a0.x, a0.y, a0.z, a0.w};
        float v1[4] = {a1.x, a1.y, a1.z, a1.w};
        float v2[4] = {a2.x, a2.y, a2.z, a2.w};
#pragma unroll
        for (int s = 0; s < 4; s++) {
            int n = 4 * n4 + s;
            float y0 = v0[s], y1 = v1[s], y2 = v2[s];
            float wv = ws[n];
            float wy0 = wv * y0, wy1 = wv * y1, wy2 = wv * y2;
            s1[0] += wy0; s1[1] += wy1; s1[2] += wy2;
            S2[0] += wy0 * y0; S2[1] += wy0 * y1; S2[2] += wy0 * y2;
            S2[3] += wy1 * y1; S2[4] += wy1 * y2; S2[5] += wy2 * y2;
            float4 q0 = bb4s[n * 6 + 0], q1 = bb4s[n * 6 + 1];
            float4 q2 = bb4s[n * 6 + 2], q3 = bb4s[n * 6 + 3];
            float4 q4 = bb4s[n * 6 + 4], q5 = bb4s[n * 6 + 5];
            float bbv[24] = {q0.x, q0.y, q0.z, q0.w, q1.x, q1.y, q1.z, q1.w,
                             q2.x, q2.y, q2.z, q2.w, q3.x, q3.y, q3.z, q3.w,
                             q4.x, q4.y, q4.z, q4.w, q5.x, q5.y, q5.z, q5.w};
#pragma unroll
            for (int k = 0; k < 8; k++) {
#pragma unroll
                for (int j = 0; j < 3; j++) {
                    float bv = bbv[k * 3 + j];
                    P[k][3 * j + 0] += bv * y0;
                    P[k][3 * j + 1] += bv * y1;
                    P[k][3 * j + 2] += bv * y2;
                }
            }
        }
    }
    float inv_wsum = __fdividef(1.f, swsum);
    float ym[3] = {s1[0] * inv_wsum, s1[1] * inv_wsum, s1[2] * inv_wsum};
    float Y2c[6];
    Y2c[0] = S2[0] - s1[0] * s1[0] * inv_wsum;
    Y2c[1] = S2[1] - s1[0] * s1[1] * inv_wsum;
    Y2c[2] = S2[2] - s1[0] * s1[2] * inv_wsum;
    Y2c[3] = S2[3] - s1[1] * s1[1] * inv_wsum;
    Y2c[4] = S2[4] - s1[1] * s1[2] * inv_wsum;
    Y2c[5] = S2[5] - s1[2] * s1[2] * inv_wsum;

    // ---- build Q, eigenvalue-only Jacobi (6 sweeps) ----
    float A_[55];
    build_S(A_, P, Gs, gs, Y2c, sQ00, 0.f);
#pragma unroll 1
    for (int sweep = 0; sweep < 6; sweep++) {
        R2(0,1) R2(0,2) R2(0,3) R2(0,4) R2(0,5) R2(0,6) R2(0,7) R2(0,8) R2(0,9)
        R2(1,2) R2(1,3) R2(1,4) R2(1,5) R2(1,6) R2(1,7) R2(1,8) R2(1,9)
        R2(2,3) R2(2,4) R2(2,5) R2(2,6) R2(2,7) R2(2,8) R2(2,9)
        R2(3,4) R2(3,5) R2(3,6) R2(3,7) R2(3,8) R2(3,9)
        R2(4,5) R2(4,6) R2(4,7) R2(4,8) R2(4,9)
        R2(5,6) R2(5,7) R2(5,8) R2(5,9)
        R2(6,7) R2(6,8) R2(6,9)
        R2(7,8) R2(7,9)
        R2(8,9)
    }
    float lam = A_[QI(0, 0)];
    float dmax = fabsf(A_[QI(0, 0)]);
#pragma unroll
    for (int i = 1; i < 10; i++) {
        float d = A_[QI(i, i)];
        lam = fminf(lam, d);
        dmax = fmaxf(dmax, fabsf(d));
    }
    // shift slightly below lam_min so S is positive definite (stable LDL^T)
    float delta = 1e-4f * dmax + 1e-20f;
    float shift = lam - delta;

    // ---- S = Q - shift*I, un-pivoted LDL^T (S is PD) ----
    build_S(A_, P, Gs, gs, Y2c, sQ00, shift);
    float invd[10];
#pragma unroll
    for (int k = 0; k < 10; k++) {
        float dk = A_[QI(k, k)];
        invd[k] = __fdividef(1.f, copysignf(fmaxf(fabsf(dk), 1e-25f), dk));
        if (k < 9) {
#pragma unroll
            for (int i = 0; i < 10; i++) {
                if (i <= k) continue;
                float Lik = A_[QI(k, i)] * invd[k];
#pragma unroll
                for (int j = 0; j < 10; j++) {
                    if (j < i) continue;
                    A_[QI(i, j)] -= Lik * A_[QI(k, j)];
                }
                A_[QI(k, i)] = Lik;   // store L
            }
        }
    }
    // seed from last column direction: L^T v = e9
    float v[10];
    v[9] = 1.f;
#pragma unroll
    for (int i = 8; i >= 0; i--) {
        float acc = 0.f;
#pragma unroll
        for (int j = 0; j < 10; j++) {
            if (j <= i) continue;
            acc += A_[QI(i, j)] * v[j];   // L[j][i]
        }
        v[i] = -acc;
    }
    // inverse-iteration refinement #1
    float x[10];
    ldl_solve(A_, invd, v, x);
    // rescale to max-norm 1, then refinement #2
    float mx = fabsf(x[0]);
#pragma unroll
    for (int i = 1; i < 10; i++) mx = fmaxf(mx, fabsf(x[i]));
    float sc = __fdividef(1.f, fmaxf(mx, 1e-30f));
#pragma unroll
    for (int i = 0; i < 10; i++) v[i] = x[i] * sc;
    ldl_solve(A_, invd, v, x);

    float inv0 = __fdividef(1.f, x[0]);
    float R_[3][3];
#pragma unroll
    for (int i = 0; i < 3; i++)
#pragma unroll
        for (int j = 0; j < 3; j++) R_[i][j] = x[1 + 3 * j + i] * inv0;

    // ---- c = g + 2*G*Pr,  Pr[k] = sum_e P[k][e]*R[e%3][e/3] ----
    float Pr[8];
#pragma unroll
    for (int k = 0; k < 8; k++) {
        float acc = 0.f;
#pragma unroll
        for (int e = 0; e < 9; e++) acc += P[k][e] * R_[e % 3][e / 3];
        Pr[k] = acc;
    }
    float c_[8];
#pragma unroll
    for (int k = 0; k < 8; k++) {
        float acc = 0.f;
#pragma unroll
        for (int k2 = 0; k2 < 8; k2++) acc += Gs[k * 8 + k2] * Pr[k2];
        c_[k] = gs[k] + 2.f * acc;
    }
    float u[3];
#pragma unroll
    for (int j = 0; j < 3; j++) {
        float acc = 0.f;
#pragma unroll
        for (int k = 0; k < 8; k++) acc += bws[k * 3 + j] * c_[k];
        u[j] = acc;
    }
    float tv[3];
#pragma unroll
    for (int i = 0; i < 3; i++)
        tv[i] = ym[i] - (R_[i][0] * u[0] + R_[i][1] * u[1] + R_[i][2] * u[2]);

    // ---- outputs: [R (B*9) | t (B*3) | c (B*8)] ----
    float* oR = out;
    float* oT = out + (size_t)Bc * 9;
    float* oC = out + (size_t)Bc * 12;
#pragma unroll
    for (int i = 0; i < 3; i++)
#pragma unroll
        for (int j = 0; j < 3; j++) oR[(size_t)b * 9 + i * 3 + j] = R_[i][j];
#pragma unroll
    for (int i = 0; i < 3; i++) oT[(size_t)b * 3 + i] = tv[i];
#pragma unroll
    for (int k = 0; k < 8; k++) oC[(size_t)b * 8 + k] = c_[k];
}

// ------------------------------ launcher -----------------------------------
extern "C" void kernel_launch(void* const* d_in, const int* in_sizes, int n_in,
                              void* d_out, int out_size) {
    const float* y = (const float*)d_in[0];
    const float* b = (const float*)d_in[1];
    const float* w = (const float*)d_in[2];
    const float* lam = (const float*)d_in[3];
    int Bc = in_sizes[0] / 192;
    pace_precompute<<<1, 256>>>(b, w, lam);
    int blocks = (Bc + 31) / 32;
    pace_main<<<blocks, 32>>>(y, w, (float*)d_out, Bc);
}